// round 12
// baseline (speedup 1.0000x reference)
#include <cuda_runtime.h>
#include <cuda_bf16.h>
#include <math.h>
#include <stdint.h>

#define Bsz 256
#define Tn  256
#define In  128
#define Hn  512
#define NCTA 128

// ---------------- device scratch ----------------
__device__ float g_xs[(size_t)Tn * Bsz * Hn];
// swizzled h images: [buf][group mg: 8][kc: 2][row: 32][512B]
__device__ uint4 g_ihi4[2][16384];
__device__ uint4 g_ilo4[2][16384];
__device__ float g_hT[Bsz * Hn];
__device__ unsigned int g_barA[8 * 32];   // kc0 producer warps (cta_n<8): 32 arrivals/step
__device__ unsigned int g_barB[8 * 32];   // kc1 producer warps (cta_n>=8)

// ---------------- helpers ----------------
__device__ __forceinline__ uint32_t smem_u32(const void* p) {
    uint32_t a;
    asm("{ .reg .u64 t; cvta.to.shared.u64 t, %1; cvt.u32.u64 %0, t; }" : "=r"(a) : "l"(p));
    return a;
}
#define MBI(addr, cnt) asm volatile("mbarrier.init.shared.b64 [%0], %1;" :: "r"(addr), "r"(cnt) : "memory")
#define MBTX(addr, bytes) asm volatile("mbarrier.arrive.expect_tx.shared.b64 _, [%0], %1;" :: "r"(addr), "r"(bytes) : "memory")
#define MBW(addr, par) do { \
    asm volatile("{\n\t.reg .pred P1;\n\tWL_%=:\n\t" \
        "mbarrier.try_wait.parity.acquire.cta.shared::cta.b64 P1, [%0], %1, 0x989680;\n\t" \
        "@P1 bra.uni WD_%=;\n\tbra.uni WL_%=;\n\tWD_%=:\n\t}" \
        :: "r"((uint32_t)(addr)), "r"((uint32_t)(par)) : "memory"); } while (0)

__device__ __forceinline__ void bulk_g2s(uint32_t dst, const void* src, uint32_t bytes, uint32_t mbar) {
    asm volatile("cp.async.bulk.shared::cta.global.mbarrier::complete_tx::bytes [%0], [%1], %2, [%3];"
        :: "r"(dst), "l"(src), "r"(bytes), "r"(mbar) : "memory");
}
__device__ __forceinline__ void ldsm4(uint32_t r[4], uint32_t addr) {
    asm volatile("ldmatrix.sync.aligned.m8n8.x4.shared.b16 {%0,%1,%2,%3}, [%4];"
                 : "=r"(r[0]), "=r"(r[1]), "=r"(r[2]), "=r"(r[3]) : "r"(addr));
}
__device__ __forceinline__ void mma_bf16(float c[4], const uint32_t a[4], uint32_t b0, uint32_t b1) {
    asm volatile("mma.sync.aligned.m16n8k16.row.col.f32.bf16.bf16.f32 "
                 "{%0,%1,%2,%3},{%4,%5,%6,%7},{%8,%9},{%0,%1,%2,%3};"
                 : "+f"(c[0]), "+f"(c[1]), "+f"(c[2]), "+f"(c[3])
                 : "r"(a[0]), "r"(a[1]), "r"(a[2]), "r"(a[3]), "r"(b0), "r"(b1));
}
__device__ __forceinline__ void bar_arrive(unsigned int* p) {
    asm volatile("red.add.release.gpu.u32 [%0], 1;" :: "l"(p) : "memory");
}
__device__ __forceinline__ uint32_t bar_ld(unsigned int* p) {
    uint32_t v;
    asm volatile("ld.acquire.gpu.u32 %0, [%1];" : "=r"(v) : "l"(p) : "memory");
    return v;
}
__device__ __forceinline__ uint32_t pack_bf16x2(float a, float b) {
    __nv_bfloat16 ha = __float2bfloat16(a), hb = __float2bfloat16(b);
    return (uint32_t)__bfloat16_as_ushort(ha) | ((uint32_t)__bfloat16_as_ushort(hb) << 16);
}
// fast tanh: 1 - 2/(e^{2x}+1). abs err ~1e-7; saturates to +-1 correctly.
__device__ __forceinline__ float ftanh(float x) {
    float e = __expf(2.0f * x);
    return 1.0f - __fdividef(2.0f, e + 1.0f);
}

// ---------------- init ----------------
__global__ void init_kernel() {
    int i = blockIdx.x * blockDim.x + threadIdx.x;
    if (i < 8 * 32) { g_barA[i] = 0u; g_barB[i] = 0u; }
    if (i < 16384) {
        g_ihi4[0][i] = make_uint4(0,0,0,0); g_ihi4[1][i] = make_uint4(0,0,0,0);
        g_ilo4[0][i] = make_uint4(0,0,0,0); g_ilo4[1][i] = make_uint4(0,0,0,0);
    }
}

// ---------------- xs GEMM: m64 x n64 tiles, 2 CTAs/SM (proven) ----------------
#define X2ROWB 272
#define X2_AHI 0
#define X2_ALO 17408
#define X2_WHI 34816
#define X2_WLO 52224
#define SMEM_X2 69632

__global__ __launch_bounds__(256, 2)
void xs_mma_kernel(const float* __restrict__ x, const float* __restrict__ W_ih,
                   const float* __restrict__ b_ih, const float* __restrict__ b_hh) {
    extern __shared__ unsigned char smem[];
    const uint32_t sb = smem_u32(smem);
    const int tid = threadIdx.x;
    const int wid = tid >> 5, lane = tid & 31;
    const int m0 = blockIdx.y * 64;
    const int n0 = blockIdx.x * 64;
    const int tt = m0 >> 8;
    const int b0 = m0 & 255;

    {
        int r = tid >> 2, seg = (tid & 3) * 32;
        const float4* src = (const float4*)(x + ((size_t)(b0 + r) * Tn + tt) * In + seg);
        uint32_t dhi = sb + X2_AHI + r * X2ROWB + seg * 2;
        uint32_t dlo = sb + X2_ALO + r * X2ROWB + seg * 2;
        #pragma unroll
        for (int q = 0; q < 8; q++) {
            float4 v = src[q];
            __nv_bfloat16 h0 = __float2bfloat16(v.x), h1 = __float2bfloat16(v.y);
            __nv_bfloat16 h2 = __float2bfloat16(v.z), h3 = __float2bfloat16(v.w);
            uint32_t hi0 = (uint32_t)__bfloat16_as_ushort(h0) | ((uint32_t)__bfloat16_as_ushort(h1) << 16);
            uint32_t hi1 = (uint32_t)__bfloat16_as_ushort(h2) | ((uint32_t)__bfloat16_as_ushort(h3) << 16);
            uint32_t lo0 = pack_bf16x2(v.x - __bfloat162float(h0), v.y - __bfloat162float(h1));
            uint32_t lo1 = pack_bf16x2(v.z - __bfloat162float(h2), v.w - __bfloat162float(h3));
            asm volatile("st.shared.v2.b32 [%0], {%1,%2};" :: "r"(dhi + q * 8), "r"(hi0), "r"(hi1));
            asm volatile("st.shared.v2.b32 [%0], {%1,%2};" :: "r"(dlo + q * 8), "r"(lo0), "r"(lo1));
        }
    }
    {
        int r = tid >> 2, seg = (tid & 3) * 32;
        const float4* src = (const float4*)(W_ih + (size_t)(n0 + r) * In + seg);
        uint32_t dhi = sb + X2_WHI + r * X2ROWB + seg * 2;
        uint32_t dlo = sb + X2_WLO + r * X2ROWB + seg * 2;
        #pragma unroll
        for (int q = 0; q < 8; q++) {
            float4 v = src[q];
            __nv_bfloat16 h0 = __float2bfloat16(v.x), h1 = __float2bfloat16(v.y);
            __nv_bfloat16 h2 = __float2bfloat16(v.z), h3 = __float2bfloat16(v.w);
            uint32_t hi0 = (uint32_t)__bfloat16_as_ushort(h0) | ((uint32_t)__bfloat16_as_ushort(h1) << 16);
            uint32_t hi1 = (uint32_t)__bfloat16_as_ushort(h2) | ((uint32_t)__bfloat16_as_ushort(h3) << 16);
            uint32_t lo0 = pack_bf16x2(v.x - __bfloat162float(h0), v.y - __bfloat162float(h1));
            uint32_t lo1 = pack_bf16x2(v.z - __bfloat162float(h2), v.w - __bfloat162float(h3));
            asm volatile("st.shared.v2.b32 [%0], {%1,%2};" :: "r"(dhi + q * 8), "r"(hi0), "r"(hi1));
            asm volatile("st.shared.v2.b32 [%0], {%1,%2};" :: "r"(dlo + q * 8), "r"(lo0), "r"(lo1));
        }
    }
    __syncthreads();

    const int wm = wid & 3, wn = wid >> 2;
    const int ja = lane >> 3, ra = lane & 7;
    const int gq = lane >> 2, tq = lane & 3;

    const uint32_t a_off = (uint32_t)(wm * 16 + (ja & 1) * 8 + ra) * X2ROWB + (uint32_t)(ja >> 1) * 16;
    uint32_t w_off[2];
    #pragma unroll
    for (int np = 0; np < 2; np++)
        w_off[np] = (uint32_t)(wn * 32 + np * 16 + (ja >> 1) * 8 + ra) * X2ROWB + (uint32_t)(ja & 1) * 16;

    float c[4][4];
    #pragma unroll
    for (int j = 0; j < 4; j++)
        #pragma unroll
        for (int q = 0; q < 4; q++) c[j][q] = 0.f;

    #pragma unroll
    for (int ks = 0; ks < 8; ks++) {
        uint32_t kb = (uint32_t)ks * 32;
        uint32_t ahi[4], alo[4], whi[2][4], wlo[2][4];
        ldsm4(ahi, sb + X2_AHI + a_off + kb);
        ldsm4(alo, sb + X2_ALO + a_off + kb);
        #pragma unroll
        for (int np = 0; np < 2; np++) {
            ldsm4(whi[np], sb + X2_WHI + w_off[np] + kb);
            ldsm4(wlo[np], sb + X2_WLO + w_off[np] + kb);
        }
        #pragma unroll
        for (int nt = 0; nt < 4; nt++) {
            int np = nt >> 1, h = (nt & 1) * 2;
            mma_bf16(c[nt], ahi, whi[np][h], whi[np][h + 1]);
            mma_bf16(c[nt], ahi, wlo[np][h], wlo[np][h + 1]);
            mma_bf16(c[nt], alo, whi[np][h], whi[np][h + 1]);
        }
    }

    __syncthreads();
    #pragma unroll
    for (int nt = 0; nt < 4; nt++) {
        int cl = wn * 32 + nt * 8 + tq * 2;
        int col = n0 + cl;
        float ba = b_ih[col] + b_hh[col];
        float bb = b_ih[col + 1] + b_hh[col + 1];
        int rl = wm * 16 + gq;
        asm volatile("st.shared.v2.f32 [%0], {%1,%2};"
            :: "r"(sb + rl * X2ROWB + cl * 4), "f"(c[nt][0] + ba), "f"(c[nt][1] + bb));
        asm volatile("st.shared.v2.f32 [%0], {%1,%2};"
            :: "r"(sb + (rl + 8) * X2ROWB + cl * 4), "f"(c[nt][2] + ba), "f"(c[nt][3] + bb));
    }
    __syncthreads();
    for (int i = tid; i < 1024; i += 256) {
        int r = i >> 4, cc = (i & 15) * 4;
        uint32_t v0, v1, v2, v3;
        asm volatile("ld.shared.v4.b32 {%0,%1,%2,%3}, [%4];"
            : "=r"(v0), "=r"(v1), "=r"(v2), "=r"(v3) : "r"(sb + r * X2ROWB + cc * 4));
        *(uint4*)(g_xs + (size_t)(m0 + r) * Hn + n0 + cc) = make_uint4(v0, v1, v2, v3);
    }
}

// ---------------- persistent recurrence: split-kc barriers + DMA warp (round-8 skeleton) ----------------
#define ROWB 1040
#define OFF_BAR 0          // full_kc0 @0, full_kc1 @8
#define OFF_WHI 1024
#define OFF_WLO 34304
#define OFF_AHI 67584
#define OFF_ALO 100352
#define SMEM_RP 133120

__global__ __launch_bounds__(160, 1)
void rnn_persist(const float* __restrict__ W_hh) {
    extern __shared__ unsigned char smem[];
    const uint32_t sb = smem_u32(smem);
    const int tid = threadIdx.x;
    const int wid = tid >> 5, lane = tid & 31;
    const int cta_m = blockIdx.x >> 4;
    const int cta_n = blockIdx.x & 15;
    const int m0 = cta_m * 32, n0 = cta_n * 32;
    unsigned int* bar_out = (cta_n < 8) ? &g_barA[cta_m * 32] : &g_barB[cta_m * 32];
    unsigned int* barA = &g_barA[cta_m * 32];
    unsigned int* barB = &g_barB[cta_m * 32];

    // W tile (resident), loaded by all 160 threads
    for (int idx = tid; idx < 32 * 512; idx += 160) {
        int r = idx / 512, k = idx & 511;
        float w = W_hh[(size_t)(n0 + r) * Hn + k];
        __nv_bfloat16 hi = __float2bfloat16(w);
        __nv_bfloat16 lo = __float2bfloat16(w - __bfloat162float(hi));
        *(__nv_bfloat16*)(smem + OFF_WHI + r * ROWB + k * 2) = hi;
        *(__nv_bfloat16*)(smem + OFF_WLO + r * ROWB + k * 2) = lo;
    }
    if (tid == 0) { MBI(sb + OFF_BAR, 1); MBI(sb + OFF_BAR + 8, 1); }
    __syncthreads();

    // MMA-warp lane constants
    const int wm = wid & 1, wn = wid >> 1;
    const int gq = lane >> 2, tq = lane & 3;
    const int ja = lane >> 3, ra = lane & 7;
    const int r0 = m0 + wm * 16 + gq;
    const int r1 = r0 + 8;
    const int r_loc = wm * 16 + (ja & 1) * 8 + ra;
    const uint32_t a_rowbase = (uint32_t)r_loc * 512;
    const uint32_t rl = (uint32_t)(r_loc & 7);
    const uint32_t uo = (uint32_t)(ja >> 1);
    const uint32_t b_off = (uint32_t)(wn * 16 + (ja >> 1) * 8 + ra) * ROWB + (uint32_t)(ja & 1) * 16;
    const int col0 = n0 + wn * 16 + tq * 2;
    const int rle0 = wm * 16 + gq;
    unsigned char* const img_hi_base = (unsigned char*)g_ihi4;
    unsigned char* const img_lo_base = (unsigned char*)g_ilo4;
    const size_t grp_off = (size_t)cta_m * 32768;

    for (int t = 0; t < Tn; t++) {
        const int rb = t & 1, wb = rb ^ 1;

        if (wid == 4) {
            if (lane == 0) {
                const unsigned char* shi = (const unsigned char*)g_ihi4[rb] + grp_off;
                const unsigned char* slo = (const unsigned char*)g_ilo4[rb] + grp_off;
                unsigned int target = (unsigned int)t * 32u;   // 8 CTAs x 4 warps per half
                if (t > 0) { while (bar_ld(barA) < target) { } }
                MBTX(sb + OFF_BAR, 32768u);
                bulk_g2s(sb + OFF_AHI, shi, 16384u, sb + OFF_BAR);
                bulk_g2s(sb + OFF_ALO, slo, 16384u, sb + OFF_BAR);
                if (t > 0) { while (bar_ld(barB) < target) { } }
                MBTX(sb + OFF_BAR + 8, 32768u);
                bulk_g2s(sb + OFF_AHI + 16384, shi + 16384, 16384u, sb + OFF_BAR + 8);
                bulk_g2s(sb + OFF_ALO + 16384, slo + 16384, 16384u, sb + OFF_BAR + 8);
            }
        } else {
            const float* xs_t = g_xs + (size_t)t * (Bsz * Hn);
            float2 xv[2][2];
            #pragma unroll
            for (int nt = 0; nt < 2; nt++) {
                xv[nt][0] = *(const float2*)(xs_t + (size_t)r0 * Hn + col0 + nt * 8);
                xv[nt][1] = *(const float2*)(xs_t + (size_t)r1 * Hn + col0 + nt * 8);
            }

            float c[2][4];
            #pragma unroll
            for (int i = 0; i < 2; i++)
                #pragma unroll
                for (int j = 0; j < 4; j++) c[i][j] = 0.f;

            #pragma unroll
            for (int kc = 0; kc < 2; kc++) {
                MBW(sb + OFF_BAR + 8 * kc, t & 1);
                #pragma unroll 8
                for (int ks2 = 0; ks2 < 16; ks2++) {
                    uint32_t u = ((uint32_t)ks2 << 1) | uo;
                    uint32_t u2 = (u & 24u) | ((u & 7u) ^ rl);
                    uint32_t aoff = ((uint32_t)kc << 14) + a_rowbase + (u2 << 4);
                    uint32_t kb = (uint32_t)(kc * 16 + ks2) * 32;
                    uint32_t ahi[4], alo[4], bhi[4], blo[4];
                    ldsm4(ahi, sb + OFF_AHI + aoff);
                    ldsm4(alo, sb + OFF_ALO + aoff);
                    ldsm4(bhi, sb + OFF_WHI + b_off + kb);
                    ldsm4(blo, sb + OFF_WLO + b_off + kb);
                    mma_bf16(c[0], ahi, bhi[0], bhi[1]);
                    mma_bf16(c[0], ahi, blo[0], blo[1]);
                    mma_bf16(c[0], alo, bhi[0], bhi[1]);
                    mma_bf16(c[1], ahi, bhi[2], bhi[3]);
                    mma_bf16(c[1], ahi, blo[2], blo[3]);
                    mma_bf16(c[1], alo, bhi[2], bhi[3]);
                }
            }

            unsigned char* ohi = img_hi_base + (size_t)wb * 262144 + grp_off;
            unsigned char* olo = img_lo_base + (size_t)wb * 262144 + grp_off;
            #pragma unroll
            for (int nt = 0; nt < 2; nt++) {
                int col = col0 + nt * 8;
                int kc = col >> 8;
                uint32_t u = (uint32_t)((col & 255) >> 3);
                #pragma unroll
                for (int hf = 0; hf < 2; hf++) {
                    int rle = rle0 + hf * 8;
                    float s0 = ftanh(c[nt][hf * 2]     + xv[nt][hf].x);
                    float s1 = ftanh(c[nt][hf * 2 + 1] + xv[nt][hf].y);
                    __nv_bfloat16 h0 = __float2bfloat16(s0);
                    __nv_bfloat16 h1 = __float2bfloat16(s1);
                    uint32_t wh = (uint32_t)__bfloat16_as_ushort(h0) | ((uint32_t)__bfloat16_as_ushort(h1) << 16);
                    uint32_t wl = pack_bf16x2(s0 - __bfloat162float(h0), s1 - __bfloat162float(h1));
                    uint32_t u2 = (u & 24u) | ((u & 7u) ^ (uint32_t)(rle & 7));
                    uint32_t off = (uint32_t)kc * 16384u + (uint32_t)rle * 512u + (u2 << 4) + (uint32_t)(tq * 4);
                    *(uint32_t*)(ohi + off) = wh;
                    *(uint32_t*)(olo + off) = wl;
                    if (t == Tn - 1)
                        *(float2*)(g_hT + (size_t)(m0 + rle) * Hn + col) = make_float2(s0, s1);
                }
            }
            // publish: per-warp release-arrive right after this warp's stores
            __threadfence();
            if (lane == 0) bar_arrive(bar_out);
        }
        __syncthreads();   // own-CTA smem buffer reuse guard (DMA must not refill before warps done)
    }
}

// ---------------- final FC ----------------
__global__ void fc_kernel(const float* __restrict__ fc_w, const float* __restrict__ fc_b,
                          float* __restrict__ out) {
    int b = blockIdx.x;
    float acc = 0.f;
    for (int k = threadIdx.x; k < Hn; k += 128)
        acc += g_hT[b * Hn + k] * fc_w[k];
    __shared__ float s[128];
    s[threadIdx.x] = acc;
    __syncthreads();
    #pragma unroll
    for (int o = 64; o > 0; o >>= 1) {
        if (threadIdx.x < o) s[threadIdx.x] += s[threadIdx.x + o];
        __syncthreads();
    }
    if (threadIdx.x == 0) out[b] = s[0] + fc_b[0];
}

extern "C" void kernel_launch(void* const* d_in, const int* in_sizes, int n_in,
                              void* d_out, int out_size) {
    const float* x    = (const float*)d_in[0];
    const float* W_ih = (const float*)d_in[1];
    const float* W_hh = (const float*)d_in[2];
    const float* b_ih = (const float*)d_in[3];
    const float* b_hh = (const float*)d_in[4];
    const float* fc_w = (const float*)d_in[5];
    const float* fc_b = (const float*)d_in[6];
    float* out = (float*)d_out;

    cudaFuncSetAttribute(xs_mma_kernel, cudaFuncAttributeMaxDynamicSharedMemorySize, SMEM_X2);
    cudaFuncSetAttribute(rnn_persist, cudaFuncAttributeMaxDynamicSharedMemorySize, SMEM_RP);

    init_kernel<<<256, 256>>>();
    dim3 gx(Hn / 64, (Tn * Bsz) / 64);   // (8, 1024)
    xs_mma_kernel<<<gx, 256, SMEM_X2>>>(x, W_ih, b_ih, b_hh);
    rnn_persist<<<NCTA, 160, SMEM_RP>>>(W_hh);
    fc_kernel<<<Bsz, 128>>>(fc_w, fc_b, out);
}

// round 13
// speedup vs baseline: 1.1557x; 1.1557x over previous
#include <cuda_runtime.h>
#include <cuda_bf16.h>
#include <math.h>
#include <stdint.h>

#define Bsz 256
#define Tn  256
#define In  128
#define Hn  512
#define NCTA 128

// ---------------- device scratch ----------------
__device__ float g_xs[(size_t)Tn * Bsz * Hn];
// swizzled h images: [buf][group mg: 8][kc: 2][row: 32][512B]
__device__ uint4 g_ihi4[2][16384];
__device__ uint4 g_ilo4[2][16384];
__device__ float g_hT[Bsz * Hn];
__device__ unsigned int g_barA[8 * 32];   // kc0 producers (cta_n<8): 8 arrivals/step
__device__ unsigned int g_barB[8 * 32];   // kc1 producers (cta_n>=8)

// ---------------- helpers ----------------
__device__ __forceinline__ uint32_t smem_u32(const void* p) {
    uint32_t a;
    asm("{ .reg .u64 t; cvta.to.shared.u64 t, %1; cvt.u32.u64 %0, t; }" : "=r"(a) : "l"(p));
    return a;
}
#define MBI(addr, cnt) asm volatile("mbarrier.init.shared.b64 [%0], %1;" :: "r"(addr), "r"(cnt) : "memory")
#define MBTX(addr, bytes) asm volatile("mbarrier.arrive.expect_tx.shared.b64 _, [%0], %1;" :: "r"(addr), "r"(bytes) : "memory")
#define MBW(addr, par) do { \
    asm volatile("{\n\t.reg .pred P1;\n\tWL_%=:\n\t" \
        "mbarrier.try_wait.parity.acquire.cta.shared::cta.b64 P1, [%0], %1, 0x989680;\n\t" \
        "@P1 bra.uni WD_%=;\n\tbra.uni WL_%=;\n\tWD_%=:\n\t}" \
        :: "r"((uint32_t)(addr)), "r"((uint32_t)(par)) : "memory"); } while (0)

__device__ __forceinline__ void bulk_g2s(uint32_t dst, const void* src, uint32_t bytes, uint32_t mbar) {
    asm volatile("cp.async.bulk.shared::cta.global.mbarrier::complete_tx::bytes [%0], [%1], %2, [%3];"
        :: "r"(dst), "l"(src), "r"(bytes), "r"(mbar) : "memory");
}
__device__ __forceinline__ void ldsm4(uint32_t r[4], uint32_t addr) {
    asm volatile("ldmatrix.sync.aligned.m8n8.x4.shared.b16 {%0,%1,%2,%3}, [%4];"
                 : "=r"(r[0]), "=r"(r[1]), "=r"(r[2]), "=r"(r[3]) : "r"(addr));
}
__device__ __forceinline__ void mma_bf16(float c[4], const uint32_t a[4], uint32_t b0, uint32_t b1) {
    asm volatile("mma.sync.aligned.m16n8k16.row.col.f32.bf16.bf16.f32 "
                 "{%0,%1,%2,%3},{%4,%5,%6,%7},{%8,%9},{%0,%1,%2,%3};"
                 : "+f"(c[0]), "+f"(c[1]), "+f"(c[2]), "+f"(c[3])
                 : "r"(a[0]), "r"(a[1]), "r"(a[2]), "r"(a[3]), "r"(b0), "r"(b1));
}
__device__ __forceinline__ void bar_arrive(unsigned int* p) {
    asm volatile("red.add.release.gpu.u32 [%0], 1;" :: "l"(p) : "memory");
}
__device__ __forceinline__ uint32_t bar_ld(unsigned int* p) {
    uint32_t v;
    asm volatile("ld.acquire.gpu.u32 %0, [%1];" : "=r"(v) : "l"(p) : "memory");
    return v;
}
__device__ __forceinline__ uint32_t pack_bf16x2(float a, float b) {
    __nv_bfloat16 ha = __float2bfloat16(a), hb = __float2bfloat16(b);
    return (uint32_t)__bfloat16_as_ushort(ha) | ((uint32_t)__bfloat16_as_ushort(hb) << 16);
}
// fast tanh: 1 - 2/(e^{2x}+1). abs err ~1e-7; saturates to +-1 correctly.
__device__ __forceinline__ float ftanh(float x) {
    float e = __expf(2.0f * x);
    return 1.0f - __fdividef(2.0f, e + 1.0f);
}

// ---------------- init ----------------
__global__ void init_kernel() {
    int i = blockIdx.x * blockDim.x + threadIdx.x;
    if (i < 8 * 32) { g_barA[i] = 0u; g_barB[i] = 0u; }
    if (i < 16384) {
        g_ihi4[0][i] = make_uint4(0,0,0,0); g_ihi4[1][i] = make_uint4(0,0,0,0);
        g_ilo4[0][i] = make_uint4(0,0,0,0); g_ilo4[1][i] = make_uint4(0,0,0,0);
    }
}

// ---------------- xs GEMM: m64 x n64 tiles, 2 CTAs/SM (proven) ----------------
#define X2ROWB 272
#define X2_AHI 0
#define X2_ALO 17408
#define X2_WHI 34816
#define X2_WLO 52224
#define SMEM_X2 69632

__global__ __launch_bounds__(256, 2)
void xs_mma_kernel(const float* __restrict__ x, const float* __restrict__ W_ih,
                   const float* __restrict__ b_ih, const float* __restrict__ b_hh) {
    extern __shared__ unsigned char smem[];
    const uint32_t sb = smem_u32(smem);
    const int tid = threadIdx.x;
    const int wid = tid >> 5, lane = tid & 31;
    const int m0 = blockIdx.y * 64;
    const int n0 = blockIdx.x * 64;
    const int tt = m0 >> 8;
    const int b0 = m0 & 255;

    {
        int r = tid >> 2, seg = (tid & 3) * 32;
        const float4* src = (const float4*)(x + ((size_t)(b0 + r) * Tn + tt) * In + seg);
        uint32_t dhi = sb + X2_AHI + r * X2ROWB + seg * 2;
        uint32_t dlo = sb + X2_ALO + r * X2ROWB + seg * 2;
        #pragma unroll
        for (int q = 0; q < 8; q++) {
            float4 v = src[q];
            __nv_bfloat16 h0 = __float2bfloat16(v.x), h1 = __float2bfloat16(v.y);
            __nv_bfloat16 h2 = __float2bfloat16(v.z), h3 = __float2bfloat16(v.w);
            uint32_t hi0 = (uint32_t)__bfloat16_as_ushort(h0) | ((uint32_t)__bfloat16_as_ushort(h1) << 16);
            uint32_t hi1 = (uint32_t)__bfloat16_as_ushort(h2) | ((uint32_t)__bfloat16_as_ushort(h3) << 16);
            uint32_t lo0 = pack_bf16x2(v.x - __bfloat162float(h0), v.y - __bfloat162float(h1));
            uint32_t lo1 = pack_bf16x2(v.z - __bfloat162float(h2), v.w - __bfloat162float(h3));
            asm volatile("st.shared.v2.b32 [%0], {%1,%2};" :: "r"(dhi + q * 8), "r"(hi0), "r"(hi1));
            asm volatile("st.shared.v2.b32 [%0], {%1,%2};" :: "r"(dlo + q * 8), "r"(lo0), "r"(lo1));
        }
    }
    {
        int r = tid >> 2, seg = (tid & 3) * 32;
        const float4* src = (const float4*)(W_ih + (size_t)(n0 + r) * In + seg);
        uint32_t dhi = sb + X2_WHI + r * X2ROWB + seg * 2;
        uint32_t dlo = sb + X2_WLO + r * X2ROWB + seg * 2;
        #pragma unroll
        for (int q = 0; q < 8; q++) {
            float4 v = src[q];
            __nv_bfloat16 h0 = __float2bfloat16(v.x), h1 = __float2bfloat16(v.y);
            __nv_bfloat16 h2 = __float2bfloat16(v.z), h3 = __float2bfloat16(v.w);
            uint32_t hi0 = (uint32_t)__bfloat16_as_ushort(h0) | ((uint32_t)__bfloat16_as_ushort(h1) << 16);
            uint32_t hi1 = (uint32_t)__bfloat16_as_ushort(h2) | ((uint32_t)__bfloat16_as_ushort(h3) << 16);
            uint32_t lo0 = pack_bf16x2(v.x - __bfloat162float(h0), v.y - __bfloat162float(h1));
            uint32_t lo1 = pack_bf16x2(v.z - __bfloat162float(h2), v.w - __bfloat162float(h3));
            asm volatile("st.shared.v2.b32 [%0], {%1,%2};" :: "r"(dhi + q * 8), "r"(hi0), "r"(hi1));
            asm volatile("st.shared.v2.b32 [%0], {%1,%2};" :: "r"(dlo + q * 8), "r"(lo0), "r"(lo1));
        }
    }
    __syncthreads();

    const int wm = wid & 3, wn = wid >> 2;
    const int ja = lane >> 3, ra = lane & 7;
    const int gq = lane >> 2, tq = lane & 3;

    const uint32_t a_off = (uint32_t)(wm * 16 + (ja & 1) * 8 + ra) * X2ROWB + (uint32_t)(ja >> 1) * 16;
    uint32_t w_off[2];
    #pragma unroll
    for (int np = 0; np < 2; np++)
        w_off[np] = (uint32_t)(wn * 32 + np * 16 + (ja >> 1) * 8 + ra) * X2ROWB + (uint32_t)(ja & 1) * 16;

    float c[4][4];
    #pragma unroll
    for (int j = 0; j < 4; j++)
        #pragma unroll
        for (int q = 0; q < 4; q++) c[j][q] = 0.f;

    #pragma unroll
    for (int ks = 0; ks < 8; ks++) {
        uint32_t kb = (uint32_t)ks * 32;
        uint32_t ahi[4], alo[4], whi[2][4], wlo[2][4];
        ldsm4(ahi, sb + X2_AHI + a_off + kb);
        ldsm4(alo, sb + X2_ALO + a_off + kb);
        #pragma unroll
        for (int np = 0; np < 2; np++) {
            ldsm4(whi[np], sb + X2_WHI + w_off[np] + kb);
            ldsm4(wlo[np], sb + X2_WLO + w_off[np] + kb);
        }
        #pragma unroll
        for (int nt = 0; nt < 4; nt++) {
            int np = nt >> 1, h = (nt & 1) * 2;
            mma_bf16(c[nt], ahi, whi[np][h], whi[np][h + 1]);
            mma_bf16(c[nt], ahi, wlo[np][h], wlo[np][h + 1]);
            mma_bf16(c[nt], alo, whi[np][h], whi[np][h + 1]);
        }
    }

    __syncthreads();
    #pragma unroll
    for (int nt = 0; nt < 4; nt++) {
        int cl = wn * 32 + nt * 8 + tq * 2;
        int col = n0 + cl;
        float ba = b_ih[col] + b_hh[col];
        float bb = b_ih[col + 1] + b_hh[col + 1];
        int rl = wm * 16 + gq;
        asm volatile("st.shared.v2.f32 [%0], {%1,%2};"
            :: "r"(sb + rl * X2ROWB + cl * 4), "f"(c[nt][0] + ba), "f"(c[nt][1] + bb));
        asm volatile("st.shared.v2.f32 [%0], {%1,%2};"
            :: "r"(sb + (rl + 8) * X2ROWB + cl * 4), "f"(c[nt][2] + ba), "f"(c[nt][3] + bb));
    }
    __syncthreads();
    for (int i = tid; i < 1024; i += 256) {
        int r = i >> 4, cc = (i & 15) * 4;
        uint32_t v0, v1, v2, v3;
        asm volatile("ld.shared.v4.b32 {%0,%1,%2,%3}, [%4];"
            : "=r"(v0), "=r"(v1), "=r"(v2), "=r"(v3) : "r"(sb + r * X2ROWB + cc * 4));
        *(uint4*)(g_xs + (size_t)(m0 + r) * Hn + n0 + cc) = make_uint4(v0, v1, v2, v3);
    }
}

// ---------------- persistent recurrence: EXACT round-8 skeleton + ftanh ----------------
#define ROWB 1040
#define OFF_BAR 0          // full_kc0 @0, full_kc1 @8
#define OFF_WHI 1024
#define OFF_WLO 34304
#define OFF_AHI 67584
#define OFF_ALO 100352
#define SMEM_RP 133120

__global__ __launch_bounds__(160, 1)
void rnn_persist(const float* __restrict__ W_hh) {
    extern __shared__ unsigned char smem[];
    const uint32_t sb = smem_u32(smem);
    const int tid = threadIdx.x;
    const int wid = tid >> 5, lane = tid & 31;
    const int cta_m = blockIdx.x >> 4;
    const int cta_n = blockIdx.x & 15;
    const int m0 = cta_m * 32, n0 = cta_n * 32;
    unsigned int* bar_out = (cta_n < 8) ? &g_barA[cta_m * 32] : &g_barB[cta_m * 32];
    unsigned int* barA = &g_barA[cta_m * 32];
    unsigned int* barB = &g_barB[cta_m * 32];

    // W tile (resident), loaded by all 160 threads
    for (int idx = tid; idx < 32 * 512; idx += 160) {
        int r = idx / 512, k = idx & 511;
        float w = W_hh[(size_t)(n0 + r) * Hn + k];
        __nv_bfloat16 hi = __float2bfloat16(w);
        __nv_bfloat16 lo = __float2bfloat16(w - __bfloat162float(hi));
        *(__nv_bfloat16*)(smem + OFF_WHI + r * ROWB + k * 2) = hi;
        *(__nv_bfloat16*)(smem + OFF_WLO + r * ROWB + k * 2) = lo;
    }
    if (tid == 0) { MBI(sb + OFF_BAR, 1); MBI(sb + OFF_BAR + 8, 1); }
    __syncthreads();

    // MMA-warp lane constants
    const int wm = wid & 1, wn = wid >> 1;
    const int gq = lane >> 2, tq = lane & 3;
    const int ja = lane >> 3, ra = lane & 7;
    const int r0 = m0 + wm * 16 + gq;
    const int r1 = r0 + 8;
    const int r_loc = wm * 16 + (ja & 1) * 8 + ra;
    const uint32_t a_rowbase = (uint32_t)r_loc * 512;
    const uint32_t rl = (uint32_t)(r_loc & 7);
    const uint32_t uo = (uint32_t)(ja >> 1);
    const uint32_t b_off = (uint32_t)(wn * 16 + (ja >> 1) * 8 + ra) * ROWB + (uint32_t)(ja & 1) * 16;
    const int col0 = n0 + wn * 16 + tq * 2;
    const int rle0 = wm * 16 + gq;
    unsigned char* const img_hi_base = (unsigned char*)g_ihi4;
    unsigned char* const img_lo_base = (unsigned char*)g_ilo4;
    const size_t grp_off = (size_t)cta_m * 32768;

    for (int t = 0; t < Tn; t++) {
        const int rb = t & 1, wb = rb ^ 1;

        if (wid == 4) {
            if (lane == 0) {
                const unsigned char* shi = (const unsigned char*)g_ihi4[rb] + grp_off;
                const unsigned char* slo = (const unsigned char*)g_ilo4[rb] + grp_off;
                unsigned int target = (unsigned int)t * 8u;
                if (t > 0) {
                    bar_arrive(bar_out);             // completion of step t-1
                    while (bar_ld(barA) < target) { }
                }
                MBTX(sb + OFF_BAR, 32768u);
                bulk_g2s(sb + OFF_AHI, shi, 16384u, sb + OFF_BAR);
                bulk_g2s(sb + OFF_ALO, slo, 16384u, sb + OFF_BAR);
                if (t > 0) { while (bar_ld(barB) < target) { } }
                MBTX(sb + OFF_BAR + 8, 32768u);
                bulk_g2s(sb + OFF_AHI + 16384, shi + 16384, 16384u, sb + OFF_BAR + 8);
                bulk_g2s(sb + OFF_ALO + 16384, slo + 16384, 16384u, sb + OFF_BAR + 8);
            }
        } else {
            const float* xs_t = g_xs + (size_t)t * (Bsz * Hn);
            float2 xv[2][2];
            #pragma unroll
            for (int nt = 0; nt < 2; nt++) {
                xv[nt][0] = *(const float2*)(xs_t + (size_t)r0 * Hn + col0 + nt * 8);
                xv[nt][1] = *(const float2*)(xs_t + (size_t)r1 * Hn + col0 + nt * 8);
            }

            float c[2][4];
            #pragma unroll
            for (int i = 0; i < 2; i++)
                #pragma unroll
                for (int j = 0; j < 4; j++) c[i][j] = 0.f;

            #pragma unroll
            for (int kc = 0; kc < 2; kc++) {
                MBW(sb + OFF_BAR + 8 * kc, t & 1);
                #pragma unroll 8
                for (int ks2 = 0; ks2 < 16; ks2++) {
                    uint32_t u = ((uint32_t)ks2 << 1) | uo;
                    uint32_t u2 = (u & 24u) | ((u & 7u) ^ rl);
                    uint32_t aoff = ((uint32_t)kc << 14) + a_rowbase + (u2 << 4);
                    uint32_t kb = (uint32_t)(kc * 16 + ks2) * 32;
                    uint32_t ahi[4], alo[4], bhi[4], blo[4];
                    ldsm4(ahi, sb + OFF_AHI + aoff);
                    ldsm4(alo, sb + OFF_ALO + aoff);
                    ldsm4(bhi, sb + OFF_WHI + b_off + kb);
                    ldsm4(blo, sb + OFF_WLO + b_off + kb);
                    mma_bf16(c[0], ahi, bhi[0], bhi[1]);
                    mma_bf16(c[0], ahi, blo[0], blo[1]);
                    mma_bf16(c[0], alo, bhi[0], bhi[1]);
                    mma_bf16(c[1], ahi, bhi[2], bhi[3]);
                    mma_bf16(c[1], ahi, blo[2], blo[3]);
                    mma_bf16(c[1], alo, bhi[2], bhi[3]);
                }
            }

            unsigned char* ohi = img_hi_base + (size_t)wb * 262144 + grp_off;
            unsigned char* olo = img_lo_base + (size_t)wb * 262144 + grp_off;
            #pragma unroll
            for (int nt = 0; nt < 2; nt++) {
                int col = col0 + nt * 8;
                int kc = col >> 8;
                uint32_t u = (uint32_t)((col & 255) >> 3);
                #pragma unroll
                for (int hf = 0; hf < 2; hf++) {
                    int rle = rle0 + hf * 8;
                    float s0 = ftanh(c[nt][hf * 2]     + xv[nt][hf].x);
                    float s1 = ftanh(c[nt][hf * 2 + 1] + xv[nt][hf].y);
                    __nv_bfloat16 h0 = __float2bfloat16(s0);
                    __nv_bfloat16 h1 = __float2bfloat16(s1);
                    uint32_t wh = (uint32_t)__bfloat16_as_ushort(h0) | ((uint32_t)__bfloat16_as_ushort(h1) << 16);
                    uint32_t wl = pack_bf16x2(s0 - __bfloat162float(h0), s1 - __bfloat162float(h1));
                    uint32_t u2 = (u & 24u) | ((u & 7u) ^ (uint32_t)(rle & 7));
                    uint32_t off = (uint32_t)kc * 16384u + (uint32_t)rle * 512u + (u2 << 4) + (uint32_t)(tq * 4);
                    *(uint32_t*)(ohi + off) = wh;
                    *(uint32_t*)(olo + off) = wl;
                    if (t == Tn - 1)
                        *(float2*)(g_hT + (size_t)(m0 + rle) * Hn + col) = make_float2(s0, s1);
                }
            }
        }
        __syncthreads();
    }
}

// ---------------- final FC ----------------
__global__ void fc_kernel(const float* __restrict__ fc_w, const float* __restrict__ fc_b,
                          float* __restrict__ out) {
    int b = blockIdx.x;
    float acc = 0.f;
    for (int k = threadIdx.x; k < Hn; k += 128)
        acc += g_hT[b * Hn + k] * fc_w[k];
    __shared__ float s[128];
    s[threadIdx.x] = acc;
    __syncthreads();
    #pragma unroll
    for (int o = 64; o > 0; o >>= 1) {
        if (threadIdx.x < o) s[threadIdx.x] += s[threadIdx.x + o];
        __syncthreads();
    }
    if (threadIdx.x == 0) out[b] = s[0] + fc_b[0];
}

extern "C" void kernel_launch(void* const* d_in, const int* in_sizes, int n_in,
                              void* d_out, int out_size) {
    const float* x    = (const float*)d_in[0];
    const float* W_ih = (const float*)d_in[1];
    const float* W_hh = (const float*)d_in[2];
    const float* b_ih = (const float*)d_in[3];
    const float* b_hh = (const float*)d_in[4];
    const float* fc_w = (const float*)d_in[5];
    const float* fc_b = (const float*)d_in[6];
    float* out = (float*)d_out;

    cudaFuncSetAttribute(xs_mma_kernel, cudaFuncAttributeMaxDynamicSharedMemorySize, SMEM_X2);
    cudaFuncSetAttribute(rnn_persist, cudaFuncAttributeMaxDynamicSharedMemorySize, SMEM_RP);

    init_kernel<<<256, 256>>>();
    dim3 gx(Hn / 64, (Tn * Bsz) / 64);   // (8, 1024)
    xs_mma_kernel<<<gx, 256, SMEM_X2>>>(x, W_ih, b_ih, b_hh);
    rnn_persist<<<NCTA, 160, SMEM_RP>>>(W_hh);
    fc_kernel<<<Bsz, 128>>>(fc_w, fc_b, out);
}